// round 1
// baseline (speedup 1.0000x reference)
#include <cuda_runtime.h>
#include <cstdint>

#define NPTS 8192
#define DIM 128
#define TPAD 132   // padded shared row stride (words) to break bank conflicts

// ---------------- scratch (device globals; no allocations allowed) ----------
__device__ float g_src[NPTS * DIM];
__device__ float g_pos[NPTS * DIM];
__device__ float g_dot[NPTS];
__device__ float g_lse_partial[128];   // [matrix(2)][row-tile(64)]
__device__ int   g_idx_is64;

// ---------------- dtype sniff: int64 vs int32 indices ------------------------
// If the buffer holds little-endian int64 values < 2^31, every odd 32-bit lane
// is zero. If it holds int32 values, odd lanes are random indices (all-zero is
// astronomically unlikely). Reads only 512B, safe for either layout.
__global__ void sniff_kernel(const int* __restrict__ u32) {
    int nz = 0;
    for (int i = 1; i < 128; i += 2) nz |= u32[i];
    g_idx_is64 = (nz == 0) ? 1 : 0;
}

// ---------------- gather + L2 normalize + align dot --------------------------
__global__ void gather_norm_kernel(const void* __restrict__ u_raw,
                                   const void* __restrict__ v_raw,
                                   const float* __restrict__ emb) {
    int i = blockIdx.x;
    int t = threadIdx.x;

    long long ui, vi;
    if (g_idx_is64) {
        ui = ((const long long*)u_raw)[i];
        vi = ((const long long*)v_raw)[i];
    } else {
        ui = ((const int*)u_raw)[i];
        vi = ((const int*)v_raw)[i];
    }

    float xu = emb[ui * DIM + t];
    float xv = emb[vi * DIM + t];

    __shared__ float red[8];
    float su2 = xu * xu, sv2 = xv * xv;
    #pragma unroll
    for (int off = 16; off; off >>= 1) {
        su2 += __shfl_down_sync(0xffffffffu, su2, off);
        sv2 += __shfl_down_sync(0xffffffffu, sv2, off);
    }
    int w = t >> 5;
    if ((t & 31) == 0) { red[w] = su2; red[4 + w] = sv2; }
    __syncthreads();
    float ssu = red[0] + red[1] + red[2] + red[3];
    float ssv = red[4] + red[5] + red[6] + red[7];

    float du = fmaxf(sqrtf(ssu), 1e-12f);
    float dv = fmaxf(sqrtf(ssv), 1e-12f);
    float su = xu / du;
    float sv = xv / dv;

    g_src[i * DIM + t] = su;
    g_pos[i * DIM + t] = sv;

    float dp = su * sv;
    #pragma unroll
    for (int off = 16; off; off >>= 1)
        dp += __shfl_down_sync(0xffffffffu, dp, off);
    __syncthreads();                 // all reads of red[] done
    if ((t & 31) == 0) red[w] = dp;
    __syncthreads();
    if (t == 0) g_dot[i] = red[0] + red[1] + red[2] + red[3];
}

// ---------------- fused Gram + exp row-sum + log -----------------------------
// grid (64, 2): x = row tile (128 rows), y = matrix select (src/pos).
// 256 threads, 8x8 microtile -> 128x128 block tile, K = 128 (full).
// Tiles stored K-major in shared: As[k][m], Bs[k][n] with stride TPAD.
__global__ void __launch_bounds__(256, 1) lse_kernel() {
    extern __shared__ float sm[];
    float* As = sm;                   // [128][TPAD]
    float* Bs = sm + 128 * TPAD;      // [128][TPAD]

    const float* e = (blockIdx.y == 0) ? g_src : g_pos;
    int tid = threadIdx.x;
    int r0 = blockIdx.x * 128;

    // load A tile (transposed), coalesced global reads
    for (int idx = tid; idx < 128 * 128; idx += 256) {
        int m = idx >> 7, k = idx & 127;
        As[k * TPAD + m] = e[(r0 + m) * DIM + k];
    }

    int tx = tid & 15, ty = tid >> 4;
    int m0 = ty * 8, n0 = tx * 8;

    float rowsum[8];
    #pragma unroll
    for (int i = 0; i < 8; i++) rowsum[i] = 0.f;

    for (int ci = 0; ci < NPTS / 128; ci++) {
        int c0 = ci * 128;
        __syncthreads();   // previous compute done (and A load on first iter)
        for (int idx = tid; idx < 128 * 128; idx += 256) {
            int n = idx >> 7, k = idx & 127;
            Bs[k * TPAD + n] = e[(c0 + n) * DIM + k];
        }
        __syncthreads();

        float acc[8][8];
        #pragma unroll
        for (int i = 0; i < 8; i++)
            #pragma unroll
            for (int j = 0; j < 8; j++) acc[i][j] = 0.f;

        #pragma unroll 4
        for (int k = 0; k < 128; k++) {
            float4 a0 = *(const float4*)&As[k * TPAD + m0];
            float4 a1 = *(const float4*)&As[k * TPAD + m0 + 4];
            float4 b0 = *(const float4*)&Bs[k * TPAD + n0];
            float4 b1 = *(const float4*)&Bs[k * TPAD + n0 + 4];
            float a[8] = {a0.x, a0.y, a0.z, a0.w, a1.x, a1.y, a1.z, a1.w};
            float b[8] = {b0.x, b0.y, b0.z, b0.w, b1.x, b1.y, b1.z, b1.w};
            #pragma unroll
            for (int i = 0; i < 8; i++)
                #pragma unroll
                for (int j = 0; j < 8; j++)
                    acc[i][j] = fmaf(a[i], b[j], acc[i][j]);
        }

        // coe = T*dot - T = 2*acc - 2; accumulate exp row sums
        #pragma unroll
        for (int i = 0; i < 8; i++) {
            float s = 0.f;
            #pragma unroll
            for (int j = 0; j < 8; j++)
                s += __expf(fmaf(2.0f, acc[i][j], -2.0f));
            rowsum[i] += s;
        }
    }

    // reduce row sums across the 16 tx-threads sharing each row (16-lane segs)
    float lsum = 0.f;
    #pragma unroll
    for (int i = 0; i < 8; i++) {
        float rv = rowsum[i];
        #pragma unroll
        for (int off = 8; off; off >>= 1)
            rv += __shfl_down_sync(0xffffffffu, rv, off, 16);
        if (tx == 0) lsum += logf(rv);
    }

    __shared__ float sred[16];
    __syncthreads();
    if (tx == 0) sred[ty] = lsum;
    __syncthreads();
    if (tid == 0) {
        float s = 0.f;
        #pragma unroll
        for (int i = 0; i < 16; i++) s += sred[i];
        g_lse_partial[blockIdx.y * 64 + blockIdx.x] = s;
    }
}

// ---------------- finalize ----------------------------------------------------
__global__ void finalize_kernel(float* __restrict__ out) {
    int tid = threadIdx.x;
    float a = 0.f, l = 0.f;
    for (int i = tid; i < NPTS; i += 256) a += g_dot[i];
    for (int i = tid; i < 128; i += 256)  l += g_lse_partial[i];
    __shared__ float ra[256], rl[256];
    ra[tid] = a; rl[tid] = l;
    __syncthreads();
    for (int s = 128; s; s >>= 1) {
        if (tid < s) { ra[tid] += ra[tid + s]; rl[tid] += rl[tid + s]; }
        __syncthreads();
    }
    if (tid == 0) {
        float align_mean = ra[0] / (float)NPTS;   // mean dot(src_i, pos_i)
        float align = 2.0f - 2.0f * align_mean;   // T - T*mean
        float unif  = rl[0] / (float)NPTS;        // sum of both matrices / N
        out[0] = 4.0f * align + 2.0f * unif;      // ALPHA*align + BETA*(u_src+u_pos)
    }
}

// ---------------- launch ------------------------------------------------------
extern "C" void kernel_launch(void* const* d_in, const int* in_sizes, int n_in,
                              void* d_out, int out_size) {
    const void*  u   = d_in[0];
    const void*  v   = d_in[1];
    const float* emb = (const float*)d_in[2];

    size_t smem = 2 * 128 * TPAD * sizeof(float);   // ~132 KB
    cudaFuncSetAttribute(lse_kernel,
                         cudaFuncAttributeMaxDynamicSharedMemorySize, (int)smem);

    sniff_kernel<<<1, 1>>>((const int*)u);
    gather_norm_kernel<<<NPTS, DIM>>>(u, v, emb);
    lse_kernel<<<dim3(64, 2), 256, smem>>>();
    finalize_kernel<<<1, 256>>>((float*)d_out);
}

// round 4
// speedup vs baseline: 7.0814x; 7.0814x over previous
#include <cuda_runtime.h>
#include <cuda_bf16.h>
#include <cstdint>

#define NPTS 8192
#define DIM 128
#define SSTRIDE 272           // smem tile row stride in bytes (136 bf16; 272%128=16 -> ldmatrix conflict-free)
#define TILE_BYTES (128 * SSTRIDE)   // 34816

// ---------------- scratch (device globals; no allocations allowed) ----------
__device__ __nv_bfloat16 g_src[NPTS * DIM];
__device__ __nv_bfloat16 g_pos[NPTS * DIM];
__device__ float g_dot[NPTS];
__device__ float g_lse_partial[128];   // [matrix(2)][row-tile(64)]
__device__ int   g_idx_is64;

// ---------------- PTX helpers ------------------------------------------------
__device__ __forceinline__ uint32_t smem_u32(const void* p) {
    uint32_t a;
    asm("{ .reg .u64 t; cvta.to.shared.u64 t, %1; cvt.u32.u64 %0, t; }"
        : "=r"(a) : "l"(p));
    return a;
}

#define CP_ASYNC16(dst, src) \
    asm volatile("cp.async.cg.shared.global [%0], [%1], 16;" :: "r"(dst), "l"(src) : "memory")
#define CP_COMMIT() asm volatile("cp.async.commit_group;" ::: "memory")
#define CP_WAIT1()  asm volatile("cp.async.wait_group 1;" ::: "memory")
#define CP_WAIT0()  asm volatile("cp.async.wait_group 0;" ::: "memory")

#define LDMATRIX_X4(r0, r1, r2, r3, addr) \
    asm volatile("ldmatrix.sync.aligned.m8n8.x4.shared.b16 {%0,%1,%2,%3}, [%4];" \
                 : "=r"(r0), "=r"(r1), "=r"(r2), "=r"(r3) : "r"(addr))
#define LDMATRIX_X2(r0, r1, addr) \
    asm volatile("ldmatrix.sync.aligned.m8n8.x2.shared.b16 {%0,%1}, [%2];" \
                 : "=r"(r0), "=r"(r1) : "r"(addr))

#define MMA16816(c0, c1, c2, c3, a0, a1, a2, a3, b0, b1) \
    asm volatile("mma.sync.aligned.m16n8k16.row.col.f32.bf16.bf16.f32 " \
                 "{%0,%1,%2,%3}, {%4,%5,%6,%7}, {%8,%9}, {%0,%1,%2,%3};" \
                 : "+f"(c0), "+f"(c1), "+f"(c2), "+f"(c3) \
                 : "r"(a0), "r"(a1), "r"(a2), "r"(a3), "r"(b0), "r"(b1))

// ---------------- dtype sniff: int64 vs int32 indices ------------------------
__global__ void sniff_kernel(const int* __restrict__ u32) {
    int nz = 0;
    for (int i = 1; i < 128; i += 2) nz |= u32[i];
    g_idx_is64 = (nz == 0) ? 1 : 0;
}

// ---------------- gather + L2 normalize + align dot (+bf16 store) ------------
__global__ void gather_norm_kernel(const void* __restrict__ u_raw,
                                   const void* __restrict__ v_raw,
                                   const float* __restrict__ emb) {
    int i = blockIdx.x;
    int t = threadIdx.x;

    long long ui, vi;
    if (g_idx_is64) {
        ui = ((const long long*)u_raw)[i];
        vi = ((const long long*)v_raw)[i];
    } else {
        ui = ((const int*)u_raw)[i];
        vi = ((const int*)v_raw)[i];
    }

    float xu = emb[ui * DIM + t];
    float xv = emb[vi * DIM + t];

    __shared__ float red[8];
    float su2 = xu * xu, sv2 = xv * xv;
    #pragma unroll
    for (int off = 16; off; off >>= 1) {
        su2 += __shfl_down_sync(0xffffffffu, su2, off);
        sv2 += __shfl_down_sync(0xffffffffu, sv2, off);
    }
    int w = t >> 5;
    if ((t & 31) == 0) { red[w] = su2; red[4 + w] = sv2; }
    __syncthreads();
    float ssu = red[0] + red[1] + red[2] + red[3];
    float ssv = red[4] + red[5] + red[6] + red[7];

    float du = fmaxf(sqrtf(ssu), 1e-12f);
    float dv = fmaxf(sqrtf(ssv), 1e-12f);
    float su = xu / du;
    float sv = xv / dv;

    g_src[i * DIM + t] = __float2bfloat16(su);
    g_pos[i * DIM + t] = __float2bfloat16(sv);

    float dp = su * sv;
    #pragma unroll
    for (int off = 16; off; off >>= 1)
        dp += __shfl_down_sync(0xffffffffu, dp, off);
    __syncthreads();
    if ((t & 31) == 0) red[w] = dp;
    __syncthreads();
    if (t == 0) g_dot[i] = red[0] + red[1] + red[2] + red[3];
}

// ---------------- fused HMMA Gram + exp row-sum ------------------------------
// grid (64, 2): x = 128-row tile, y = matrix (src/pos). 256 threads = 8 warps
// in a 2(m) x 4(n) arrangement; warp tile 64x32 = 4x4 m16n8k16 fragments.
// A tile loaded once; B tiles double-buffered via cp.async.
// SMEM: [A tile 34816][B0 34816][B1 34816]; A region reused for reductions.
#define SM_A  0
#define SM_B0 TILE_BYTES
#define SM_B1 (2 * TILE_BYTES)
#define SM_TOTAL (3 * TILE_BYTES)

__device__ __forceinline__ void load_tile(uint32_t sdst, const uint4* eg,
                                          int row0, int tid) {
    #pragma unroll
    for (int it = 0; it < 8; it++) {
        int idx = tid + it * 256;
        int r = idx >> 4, c = idx & 15;
        CP_ASYNC16(sdst + r * SSTRIDE + c * 16, eg + (row0 + r) * 16 + c);
    }
}

__global__ void __launch_bounds__(256, 1) lse_kernel() {
    extern __shared__ char smem[];
    const uint32_t sbase = smem_u32(smem);
    const int tid = threadIdx.x;
    const int wid = tid >> 5;
    const int lane = tid & 31;
    const int warp_m = wid >> 2;          // 0..1 -> 64 rows each
    const int warp_n = wid & 3;           // 0..3 -> 32 cols each
    const int m_base = warp_m * 64;
    const int n_base = warp_n * 32;

    const __nv_bfloat16* e = (blockIdx.y == 0) ? g_src : g_pos;
    const uint4* eg = (const uint4*)e;
    const int r0 = blockIdx.x * 128;

    // prologue: A + B0 in group0, B1 in group1
    load_tile(sbase + SM_A, eg, r0, tid);
    load_tile(sbase + SM_B0, eg, 0, tid);
    CP_COMMIT();
    load_tile(sbase + SM_B1, eg, 128, tid);
    CP_COMMIT();

    // per-lane ldmatrix base offsets
    const int l15 = lane & 15;
    const uint32_t aAddr0 = sbase + SM_A +
        (uint32_t)(m_base + l15) * SSTRIDE + (uint32_t)(lane >> 4) * 16;
    const uint32_t bOff0 =
        (uint32_t)(n_base + (l15 & 7)) * SSTRIDE + (uint32_t)(l15 >> 3) * 16;

    float acc[4][4][4];
    #pragma unroll
    for (int mt = 0; mt < 4; mt++)
        #pragma unroll
        for (int nt = 0; nt < 4; nt++)
            #pragma unroll
            for (int q = 0; q < 4; q++) acc[mt][nt][q] = 0.f;

    float rowsum[8];
    #pragma unroll
    for (int j = 0; j < 8; j++) rowsum[j] = 0.f;

    for (int i = 0; i < NPTS / 128; i++) {
        if (i < 63) { CP_WAIT1(); } else { CP_WAIT0(); }
        __syncthreads();

        const uint32_t bAddr0 = sbase + ((i & 1) ? SM_B1 : SM_B0) + bOff0;

        #pragma unroll
        for (int k = 0; k < 8; k++) {
            uint32_t a[4][4];
            #pragma unroll
            for (int mt = 0; mt < 4; mt++)
                LDMATRIX_X4(a[mt][0], a[mt][1], a[mt][2], a[mt][3],
                            aAddr0 + mt * (16 * SSTRIDE) + k * 32);
            uint32_t b[4][2];
            #pragma unroll
            for (int nt = 0; nt < 4; nt++)
                LDMATRIX_X2(b[nt][0], b[nt][1],
                            bAddr0 + nt * (8 * SSTRIDE) + k * 32);
            #pragma unroll
            for (int mt = 0; mt < 4; mt++)
                #pragma unroll
                for (int nt = 0; nt < 4; nt++)
                    MMA16816(acc[mt][nt][0], acc[mt][nt][1],
                             acc[mt][nt][2], acc[mt][nt][3],
                             a[mt][0], a[mt][1], a[mt][2], a[mt][3],
                             b[nt][0], b[nt][1]);
        }

        // fused epilogue: coe = 2*dot - 2; rowsum += exp(coe); re-zero acc
        #pragma unroll
        for (int mt = 0; mt < 4; mt++) {
            float s0 = 0.f, s1 = 0.f;
            #pragma unroll
            for (int nt = 0; nt < 4; nt++) {
                s0 += __expf(fmaf(2.0f, acc[mt][nt][0], -2.0f));
                s0 += __expf(fmaf(2.0f, acc[mt][nt][1], -2.0f));
                s1 += __expf(fmaf(2.0f, acc[mt][nt][2], -2.0f));
                s1 += __expf(fmaf(2.0f, acc[mt][nt][3], -2.0f));
                acc[mt][nt][0] = 0.f; acc[mt][nt][1] = 0.f;
                acc[mt][nt][2] = 0.f; acc[mt][nt][3] = 0.f;
            }
            rowsum[mt * 2]     += s0;
            rowsum[mt * 2 + 1] += s1;
        }

        __syncthreads();
        if (i < 62) {
            load_tile(sbase + ((i & 1) ? SM_B1 : SM_B0), eg, (i + 2) * 128, tid);
            CP_COMMIT();
        }
    }

    // ---- reduction: quad lanes share the same rows ----
    #pragma unroll
    for (int j = 0; j < 8; j++) {
        rowsum[j] += __shfl_xor_sync(0xffffffffu, rowsum[j], 1);
        rowsum[j] += __shfl_xor_sync(0xffffffffu, rowsum[j], 2);
    }

    float* red = (float*)smem;            // reuse A region: red[warp_n][128]
    if ((lane & 3) == 0) {
        #pragma unroll
        for (int mt = 0; mt < 4; mt++) {
            int row = m_base + mt * 16 + (lane >> 2);
            red[warp_n * 128 + row]     = rowsum[mt * 2];
            red[warp_n * 128 + row + 8] = rowsum[mt * 2 + 1];
        }
    }
    __syncthreads();
    if (tid < 128) {
        float s = red[tid] + red[128 + tid] + red[256 + tid] + red[384 + tid];
        red[512 + tid] = logf(s);
    }
    __syncthreads();
    if (tid == 0) {
        float ssum = 0.f;
        #pragma unroll
        for (int k = 0; k < 128; k++) ssum += red[512 + k];
        g_lse_partial[blockIdx.y * 64 + blockIdx.x] = ssum;
    }
}

// ---------------- finalize ----------------------------------------------------
__global__ void finalize_kernel(float* __restrict__ out) {
    int tid = threadIdx.x;
    float a = 0.f, l = 0.f;
    for (int i = tid; i < NPTS; i += 256) a += g_dot[i];
    for (int i = tid; i < 128; i += 256)  l += g_lse_partial[i];
    __shared__ float ra[256], rl[256];
    ra[tid] = a; rl[tid] = l;
    __syncthreads();
    for (int s = 128; s; s >>= 1) {
        if (tid < s) { ra[tid] += ra[tid + s]; rl[tid] += rl[tid + s]; }
        __syncthreads();
    }
    if (tid == 0) {
        float align_mean = ra[0] / (float)NPTS;
        float align = 2.0f - 2.0f * align_mean;
        float unif  = rl[0] / (float)NPTS;
        out[0] = 4.0f * align + 2.0f * unif;
    }
}

// ---------------- launch ------------------------------------------------------
extern "C" void kernel_launch(void* const* d_in, const int* in_sizes, int n_in,
                              void* d_out, int out_size) {
    const void*  u   = d_in[0];
    const void*  v   = d_in[1];
    const float* emb = (const float*)d_in[2];

    cudaFuncSetAttribute(lse_kernel,
                         cudaFuncAttributeMaxDynamicSharedMemorySize, SM_TOTAL);

    sniff_kernel<<<1, 1>>>((const int*)u);
    gather_norm_kernel<<<NPTS, DIM>>>(u, v, emb);
    lse_kernel<<<dim3(64, 2), 256, SM_TOTAL>>>();
    finalize_kernel<<<1, 256>>>((float*)d_out);
}